// round 13
// baseline (speedup 1.0000x reference)
#include <cuda_runtime.h>
#include <cstdint>

#define NN 100000
#define EE 1664000   // capacity margin over 1,600,000
#define DD 128

#define BGRID 592            // 4 * 148 SMs -> all resident (launch_bounds 4)
#define BTPB  256
#define BNTH  (BGRID * BTPB) // 151552 threads
#define MAXE_T 11            // covers E <= 1,667,072

// ---------------- scratch (device globals; no allocation allowed) ------------
__device__ float2 g_degcnt[NN];   // .x = weighted degree (incl self), .y = cnt
__device__ float g_dinv[NN];
__device__ int   g_rowptr[NN + 1];
__device__ int   g_fill[NN];
__device__ int   g_bsum[128];     // per-block sums for scan (98 used)
__device__ int   g_sync;          // grid barrier counter (reset in init)
__device__ int2  g_edge[EE];      // CSR: (src, norm-bits), grouped by dst
__device__ float g_h[(size_t)NN * DD];   // layer-1 X @ W1 (fp32)
__device__ float g_h2[(size_t)NN * DD];  // layer-2 pre-agg
__device__ int   g_is64;

// ---------------- helpers ----------------------------------------------------
__device__ __forceinline__ unsigned long long pack2(float v) {
    unsigned long long r;
    asm("mov.b64 %0, {%1, %1};" : "=l"(r) : "f"(v));
    return r;
}
__device__ __forceinline__ void ffma2(unsigned long long& d,
                                      unsigned long long a,
                                      unsigned long long b) {
    asm("fma.rn.f32x2 %0, %1, %2, %0;" : "+l"(d) : "l"(a), "l"(b));
}
__device__ __forceinline__ void red_add_v2(float2* addr, float a, float b) {
    asm volatile("red.global.add.v2.f32 [%0], {%1,%2};"
                 :: "l"(addr), "f"(a), "f"(b) : "memory");
}
// grid barrier (all BGRID blocks resident by construction)
__device__ __forceinline__ void gsync(int target) {
    __syncthreads();
    if (threadIdx.x == 0) {
        __threadfence();
        atomicAdd(&g_sync, 1);
        while (atomicAdd(&g_sync, 0) < target) { }
        __threadfence();
    }
    __syncthreads();
}

// ---------------- preprocessing ----------------------------------------------

// dtype sniff (int64 indices < 1e5 -> odd words zero) + per-node init
__global__ void init_kernel(const int* __restrict__ ei, int n) {
    int i = blockIdx.x * blockDim.x + threadIdx.x;
    if (i == 0) {
        int ok = 1;
        #pragma unroll
        for (int j = 1; j < 128; j += 2)
            if (ei[j] != 0) ok = 0;
        g_is64 = ok;
        g_sync = 0;                // reset grid barrier for this invocation
    }
    if (i < n) g_degcnt[i] = make_float2(1.0f, 0.0f);  // self-loop weight 1
}

// persistent CSR build: degree -> scan -> scatter, one launch, reg-cached edges
__global__ void __launch_bounds__(BTPB, 4)
build_kernel(const int* __restrict__ ei, const float* __restrict__ ew,
             int E, int nScan, int n) {
    __shared__ int sd[256];
    __shared__ int s_boff;
    int tid = threadIdx.x;
    int gthread = blockIdx.x * BTPB + tid;
    bool is64 = (g_is64 != 0);

    // ---- phase 1: degree accumulate; cache (src,dst) in registers ----
    int se[MAXE_T], de[MAXE_T];
    #pragma unroll
    for (int k = 0; k < MAXE_T; k++) {
        int e = gthread + k * BNTH;
        if (e < E) {
            int s_, d_;
            if (is64) { s_ = __ldg(ei + 2 * e); d_ = __ldg(ei + 2 * (E + e)); }
            else      { s_ = __ldg(ei + e);     d_ = __ldg(ei + E + e); }
            se[k] = s_; de[k] = d_;
            red_add_v2(&g_degcnt[d_], __ldg(ew + e), 1.0f);
        } else { se[k] = 0; de[k] = -1; }
    }
    gsync(BGRID);

    // ---- phase 2a: per-block scan over counts (blocks 0..nScan-1) ----
    int c[4]; int base = blockIdx.x * 1024 + tid * 4;
    if (blockIdx.x < nScan) {
        int s = 0;
        #pragma unroll
        for (int j = 0; j < 4; j++) {
            if (base + j < n) {
                float2 dc = g_degcnt[base + j];
                c[j] = (int)dc.y;
                g_dinv[base + j] = rsqrtf(dc.x);   // deg >= 1 always
            } else c[j] = 0;
            s += c[j];
        }
        sd[tid] = s; __syncthreads();
        for (int off = 1; off < 256; off <<= 1) {
            int v = (tid >= off) ? sd[tid - off] : 0;
            __syncthreads();
            sd[tid] += v;
            __syncthreads();
        }
        if (tid == 0) g_bsum[blockIdx.x] = sd[255];
    }
    gsync(2 * BGRID);

    // ---- phase 2b: block offsets + write rowptr/fill ----
    if (blockIdx.x < nScan) {
        if (tid < 32) {
            int carry = 0, myoff = 0;
            for (int b0 = 0; b0 < nScan; b0 += 32) {
                int idx = b0 + tid;
                int orig = (idx < nScan) ? g_bsum[idx] : 0;
                int v = orig;
                #pragma unroll
                for (int off = 1; off < 32; off <<= 1) {
                    int t = __shfl_up_sync(0xffffffffu, v, off);
                    if (tid >= off) v += t;
                }
                if (idx == blockIdx.x) myoff = carry + v - orig;
                carry += __shfl_sync(0xffffffffu, v, 31);
            }
            int lanehit = blockIdx.x & 31;
            int bcast = __shfl_sync(0xffffffffu, myoff, lanehit);
            if (tid == 0) s_boff = bcast;
        }
        __syncthreads();
        int run = s_boff + ((tid == 0) ? 0 : sd[tid - 1]);
        #pragma unroll
        for (int j = 0; j < 4; j++) {
            if (base + j < n) {
                g_rowptr[base + j] = run;
                g_fill[base + j]   = run;
                run += c[j];
            }
        }
        if (blockIdx.x == 0 && tid == 0) g_rowptr[n] = E;
    }
    gsync(3 * BGRID);

    // ---- phase 3: scatter (src/dst from registers; only ew re-read) ----
    #pragma unroll
    for (int k = 0; k < MAXE_T; k++) {
        int e = gthread + k * BNTH;
        if (e < E) {
            int s_ = se[k], d_ = de[k];
            float nm = g_dinv[s_] * __ldg(ew + e) * g_dinv[d_];
            int pos = atomicAdd(&g_fill[d_], 1);
            g_edge[pos] = make_int2(s_, __float_as_int(nm));
        }
    }
}

// ---------------- device helper: aggregate one node into a float4 ------------
__device__ __forceinline__ float4 agg_node(const float4* __restrict__ h4,
                                           int d, int lane, float4 bv) {
    const int2* ep = (const int2*)g_edge;
    float dv = g_dinv[d];
    float self = dv * dv;

    float4 a0 = __ldg(h4 + (size_t)d * 32 + lane);
    a0.x *= self; a0.y *= self; a0.z *= self; a0.w *= self;
    float4 a1 = make_float4(0.f, 0.f, 0.f, 0.f);
    float4 a2 = make_float4(0.f, 0.f, 0.f, 0.f);
    float4 a3 = make_float4(0.f, 0.f, 0.f, 0.f);

    int i   = g_rowptr[d];
    int end = g_rowptr[d + 1];

    for (; i + 4 <= end; i += 4) {
        int2 e0 = __ldg(ep + i);
        int2 e1 = __ldg(ep + i + 1);
        int2 e2 = __ldg(ep + i + 2);
        int2 e3 = __ldg(ep + i + 3);
        float4 h0 = __ldg(h4 + (size_t)e0.x * 32 + lane);
        float4 h1 = __ldg(h4 + (size_t)e1.x * 32 + lane);
        float4 h2 = __ldg(h4 + (size_t)e2.x * 32 + lane);
        float4 h3 = __ldg(h4 + (size_t)e3.x * 32 + lane);
        float n0 = __int_as_float(e0.y), n1 = __int_as_float(e1.y);
        float n2 = __int_as_float(e2.y), n3 = __int_as_float(e3.y);
        a0.x = fmaf(h0.x, n0, a0.x); a0.y = fmaf(h0.y, n0, a0.y);
        a0.z = fmaf(h0.z, n0, a0.z); a0.w = fmaf(h0.w, n0, a0.w);
        a1.x = fmaf(h1.x, n1, a1.x); a1.y = fmaf(h1.y, n1, a1.y);
        a1.z = fmaf(h1.z, n1, a1.z); a1.w = fmaf(h1.w, n1, a1.w);
        a2.x = fmaf(h2.x, n2, a2.x); a2.y = fmaf(h2.y, n2, a2.y);
        a2.z = fmaf(h2.z, n2, a2.z); a2.w = fmaf(h2.w, n2, a2.w);
        a3.x = fmaf(h3.x, n3, a3.x); a3.y = fmaf(h3.y, n3, a3.y);
        a3.z = fmaf(h3.z, n3, a3.z); a3.w = fmaf(h3.w, n3, a3.w);
    }
    for (; i < end; i++) {
        int2 e0 = __ldg(ep + i);
        float4 h0 = __ldg(h4 + (size_t)e0.x * 32 + lane);
        float n0 = __int_as_float(e0.y);
        a0.x = fmaf(h0.x, n0, a0.x); a0.y = fmaf(h0.y, n0, a0.y);
        a0.z = fmaf(h0.z, n0, a0.z); a0.w = fmaf(h0.w, n0, a0.w);
    }
    a0.x += a1.x + a2.x + a3.x;
    a0.y += a1.y + a2.y + a3.y;
    a0.z += a1.z + a2.z + a3.z;
    a0.w += a1.w + a2.w + a3.w;

    a0.x = fmaxf(a0.x + bv.x, 0.f);
    a0.y = fmaxf(a0.y + bv.y, 0.f);
    a0.z = fmaxf(a0.z + bv.z, 0.f);
    a0.w = fmaxf(a0.w + bv.w, 0.f);
    return a0;
}

// ---------------- GEMM: H[n,128] = X[n,128] @ W[128,128] ---------------------
__global__ void gemm128_kernel(const float* __restrict__ X,
                               const float* __restrict__ W,
                               float* __restrict__ H, int n) {
    int warp = (blockIdx.x * blockDim.x + threadIdx.x) >> 5;
    int lane = threadIdx.x & 31;
    int r0 = warp * 4;
    if (r0 >= n) return;

    const float4*     X4 = (const float4*)X;
    const ulonglong2* Wp = (const ulonglong2*)W;   // W row = 32 x 16B

    float4 xr[4];
    #pragma unroll
    for (int r = 0; r < 4; r++) {
        int row = (r0 + r < n) ? (r0 + r) : r0;
        xr[r] = __ldcs(X4 + (size_t)row * 32 + lane);
    }

    unsigned long long acc[4][2] = {};

    #pragma unroll 2
    for (int kb = 0; kb < 32; kb++) {
        float a[4][4];
        #pragma unroll
        for (int r = 0; r < 4; r++) {
            a[r][0] = __shfl_sync(0xffffffffu, xr[r].x, kb);
            a[r][1] = __shfl_sync(0xffffffffu, xr[r].y, kb);
            a[r][2] = __shfl_sync(0xffffffffu, xr[r].z, kb);
            a[r][3] = __shfl_sync(0xffffffffu, xr[r].w, kb);
        }
        #pragma unroll
        for (int c = 0; c < 4; c++) {
            ulonglong2 w = __ldg(Wp + (size_t)(kb * 4 + c) * 32 + lane);
            #pragma unroll
            for (int r = 0; r < 4; r++) {
                unsigned long long av = pack2(a[r][c]);
                ffma2(acc[r][0], av, w.x);
                ffma2(acc[r][1], av, w.y);
            }
        }
    }
    #pragma unroll
    for (int r = 0; r < 4; r++) {
        if (r0 + r < n)
            ((ulonglong2*)H)[(size_t)(r0 + r) * 32 + lane] =
                make_ulonglong2(acc[r][0], acc[r][1]);
    }
}

// ------- fused: agg layer-1 (4 nodes/warp) + bias/relu + GEMM with W2 --------
__global__ void agg_gemm_kernel(const float* __restrict__ h,
                                const float* __restrict__ b,
                                const float* __restrict__ W,
                                float* __restrict__ Hout, int n) {
    int warp = (blockIdx.x * blockDim.x + threadIdx.x) >> 5;
    int lane = threadIdx.x & 31;
    int d0 = warp * 4;
    if (d0 >= n) return;

    const float4* h4 = (const float4*)h;
    float4 bv = __ldg((const float4*)b + lane);

    float4 yr[4];
    #pragma unroll
    for (int r = 0; r < 4; r++) {
        int d = d0 + r;
        if (d < n) yr[r] = agg_node(h4, d, lane, bv);
        else       yr[r] = make_float4(0.f, 0.f, 0.f, 0.f);
    }

    const ulonglong2* Wp = (const ulonglong2*)W;
    unsigned long long acc[4][2] = {};

    #pragma unroll 2
    for (int kb = 0; kb < 32; kb++) {
        float a[4][4];
        #pragma unroll
        for (int r = 0; r < 4; r++) {
            a[r][0] = __shfl_sync(0xffffffffu, yr[r].x, kb);
            a[r][1] = __shfl_sync(0xffffffffu, yr[r].y, kb);
            a[r][2] = __shfl_sync(0xffffffffu, yr[r].z, kb);
            a[r][3] = __shfl_sync(0xffffffffu, yr[r].w, kb);
        }
        #pragma unroll
        for (int c = 0; c < 4; c++) {
            ulonglong2 w = __ldg(Wp + (size_t)(kb * 4 + c) * 32 + lane);
            #pragma unroll
            for (int r = 0; r < 4; r++) {
                unsigned long long av = pack2(a[r][c]);
                ffma2(acc[r][0], av, w.x);
                ffma2(acc[r][1], av, w.y);
            }
        }
    }
    #pragma unroll
    for (int r = 0; r < 4; r++) {
        if (d0 + r < n)
            ((ulonglong2*)Hout)[(size_t)(d0 + r) * 32 + lane] =
                make_ulonglong2(acc[r][0], acc[r][1]);
    }
}

// ---------------- final aggregation (layer 2) + bias + relu -> out -----------
__global__ void agg_kernel(const float* __restrict__ h,
                           const float* __restrict__ b,
                           float* __restrict__ out, int n) {
    int d = (int)(((size_t)blockIdx.x * blockDim.x + threadIdx.x) >> 5);
    int lane = threadIdx.x & 31;
    if (d >= n) return;
    float4 bv = __ldg((const float4*)b + lane);
    float4 a = agg_node((const float4*)h, d, lane, bv);
    __stcs((float4*)out + (size_t)d * 32 + lane, a);   // never re-read
}

// ---------------- launch -----------------------------------------------------
extern "C" void kernel_launch(void* const* d_in, const int* in_sizes, int n_in,
                              void* d_out, int out_size) {
    const float* x  = (const float*)d_in[0];
    const int*   ei = (const int*)d_in[1];
    const float* ew = (const float*)d_in[2];
    const float* W1 = (const float*)d_in[3];
    const float* b1 = (const float*)d_in[4];
    const float* W2 = (const float*)d_in[5];
    const float* b2 = (const float*)d_in[6];
    float* out = (float*)d_out;

    const int N = in_sizes[0] / DD;   // 100000
    const int E = in_sizes[2];        // 1600000

    float* h  = nullptr; cudaGetSymbolAddress((void**)&h,  g_h);
    float* h2 = nullptr; cudaGetSymbolAddress((void**)&h2, g_h2);

    // side stream + fork/join events (host-side objects, created once)
    static cudaStream_t sB = nullptr;
    static cudaEvent_t evFork = nullptr, evJoin = nullptr;
    if (sB == nullptr) {
        cudaStreamCreateWithFlags(&sB, cudaStreamNonBlocking);
        cudaEventCreateWithFlags(&evFork, cudaEventDisableTiming);
        cudaEventCreateWithFlags(&evJoin, cudaEventDisableTiming);
    }

    const int T = 256;
    int nodeBlocks = (N + T - 1) / T;
    int scanBlocks = (N + 1023) / 1024;                    // 98 (< BGRID)
    int quadBlocks = (((N + 3) / 4) * 32 + T - 1) / T;     // 4 rows/warp
    int aggBlocks  = (int)(((size_t)N * 32 + T - 1) / T);  // warp/node

    // fork: gemm1 (FMA-bound, deps only x/W1) overlaps LTS-bound CSR build
    cudaEventRecord(evFork, 0);
    cudaStreamWaitEvent(sB, evFork, 0);
    gemm128_kernel<<<quadBlocks, T, 0, sB>>>(x, W1, h, N);
    cudaEventRecord(evJoin, sB);

    // main stream: init + one persistent CSR build kernel
    init_kernel<<<nodeBlocks, T>>>(ei, N);
    build_kernel<<<BGRID, BTPB>>>(ei, ew, E, scanBlocks, N);

    // join: agg_gemm needs both CSR (main) and h (side)
    cudaStreamWaitEvent(0, evJoin, 0);

    // ---- fused: layer-1 aggregation + relu/bias + layer-2 GEMM ----
    agg_gemm_kernel<<<quadBlocks, T>>>(h, b1, W2, h2, N);

    // ---- layer 2 aggregation -> output ----
    agg_kernel<<<aggBlocks, T>>>(h2, b2, out, N);
}

// round 14
// speedup vs baseline: 1.0376x; 1.0376x over previous
#include <cuda_runtime.h>
#include <cstdint>

#define NN 100000
#define EE 1800000   // padded capacity: E + up to N pad slots
#define DD 128

// ---------------- scratch (device globals; no allocation allowed) ------------
__device__ float2 g_degcnt[NN];   // .x = weighted degree (incl self), .y = cnt
__device__ float g_dinv[NN];
__device__ int   g_rowptr[NN + 1];
__device__ int   g_fill[NN];
__device__ int   g_bsum[128];     // per-block sums for scan (98 used)
__device__ int   g_scan_done;     // fence+spin counter (reset in init)
__device__ int4  g_edge4[EE / 2]; // CSR: (src, norm-bits) pairs, 16B-aligned
__device__ float g_h[(size_t)NN * DD];   // layer-1 X @ W1 (fp32)
__device__ float g_h2[(size_t)NN * DD];  // layer-2 pre-agg
__device__ int   g_is64;

// ---------------- helpers ----------------------------------------------------
__device__ __forceinline__ unsigned long long pack2(float v) {
    unsigned long long r;
    asm("mov.b64 %0, {%1, %1};" : "=l"(r) : "f"(v));
    return r;
}
__device__ __forceinline__ void ffma2(unsigned long long& d,
                                      unsigned long long a,
                                      unsigned long long b) {
    asm("fma.rn.f32x2 %0, %1, %2, %0;" : "+l"(d) : "l"(a), "l"(b));
}
__device__ __forceinline__ void red_add_v2(float2* addr, float a, float b) {
    asm volatile("red.global.add.v2.f32 [%0], {%1,%2};"
                 :: "l"(addr), "f"(a), "f"(b) : "memory");
}

// ---------------- preprocessing ----------------------------------------------

// dtype sniff (int64 indices < 1e5 -> odd words zero) + per-node init
__global__ void init_kernel(const int* __restrict__ ei, int n) {
    int i = blockIdx.x * blockDim.x + threadIdx.x;
    if (i == 0) {
        int ok = 1;
        #pragma unroll
        for (int j = 1; j < 128; j += 2)
            if (ei[j] != 0) ok = 0;
        g_is64 = ok;
        g_scan_done = 0;
    }
    if (i < n) g_degcnt[i] = make_float2(1.0f, 0.0f);  // self-loop weight 1
}

// weighted degree + edge count: ONE packed v2 reduction per edge
__global__ void deg_edge_kernel(const int* __restrict__ ei,
                                const float* __restrict__ ew, int E) {
    int e = blockIdx.x * blockDim.x + threadIdx.x;
    if (e >= E) return;
    int d = g_is64 ? __ldg(ei + 2 * (E + e)) : __ldg(ei + E + e);
    red_add_v2(&g_degcnt[d], __ldg(ew + e), 1.0f);
}

// single-kernel scan over EVEN-PADDED counts: per-block scan + fence/spin.
// Rows padded to even length; pad slot zeroed here (before scatter).
__global__ void scan_all(int nblocks, int n) {
    __shared__ int sd[256];
    __shared__ int s_boff;
    int tid = threadIdx.x;
    int base = blockIdx.x * 1024 + tid * 4;
    int2* ep = (int2*)g_edge4;

    // load counts (+ write dinv on the same pass); pad to even
    int c[4], cp[4]; int s = 0;
    #pragma unroll
    for (int j = 0; j < 4; j++) {
        if (base + j < n) {
            float2 dc = g_degcnt[base + j];
            c[j]  = (int)dc.y;
            cp[j] = (c[j] + 1) & ~1;
            g_dinv[base + j] = rsqrtf(dc.x);   // deg >= 1 always
        } else { c[j] = 0; cp[j] = 0; }
        s += cp[j];
    }

    // block-wide inclusive scan of per-thread padded sums
    sd[tid] = s; __syncthreads();
    for (int off = 1; off < 256; off <<= 1) {
        int v = (tid >= off) ? sd[tid - off] : 0;
        __syncthreads();
        sd[tid] += v;
        __syncthreads();
    }
    int blockTotal = sd[255];

    // publish block total, wait for all blocks (98 <= 148 SMs, all resident)
    if (tid == 0) {
        g_bsum[blockIdx.x] = blockTotal;
        __threadfence();
        atomicAdd(&g_scan_done, 1);
        while (atomicAdd(&g_scan_done, 0) < nblocks) { }
    }
    __syncthreads();

    // warp 0: exclusive prefix of g_bsum up to blockIdx.x
    if (tid < 32) {
        int carry = 0, myoff = 0;
        for (int b0 = 0; b0 < nblocks; b0 += 32) {
            int idx = b0 + tid;
            int orig = (idx < nblocks) ? g_bsum[idx] : 0;
            int v = orig;
            #pragma unroll
            for (int off = 1; off < 32; off <<= 1) {
                int t = __shfl_up_sync(0xffffffffu, v, off);
                if (tid >= off) v += t;
            }
            if (idx == blockIdx.x) myoff = carry + v - orig;
            carry += __shfl_sync(0xffffffffu, v, 31);
        }
        int lanehit = blockIdx.x & 31;
        int bcast = __shfl_sync(0xffffffffu, myoff, lanehit);
        if (tid == 0) s_boff = bcast;
    }
    __syncthreads();

    int run = s_boff + ((tid == 0) ? 0 : sd[tid - 1]);
    #pragma unroll
    for (int j = 0; j < 4; j++) {
        if (base + j < n) {
            g_rowptr[base + j] = run;
            g_fill[base + j]   = run;
            if (c[j] & 1) ep[run + c[j]] = make_int2(0, 0);  // zero the pad
            run += cp[j];
        }
    }
    // thread covering node n-1 writes the padded grand total
    if (base < n && base + 4 >= n) g_rowptr[n] = run;
}

// scatter edges into CSR grouped by dst, with precomputed norm
__global__ void scatter_kernel(const int* __restrict__ ei,
                               const float* __restrict__ ew, int E) {
    int e = blockIdx.x * blockDim.x + threadIdx.x;
    if (e >= E) return;
    int s, d;
    if (g_is64) { s = __ldg(ei + 2 * e); d = __ldg(ei + 2 * (E + e)); }
    else        { s = __ldg(ei + e);     d = __ldg(ei + E + e); }
    float nm = g_dinv[s] * __ldg(ew + e) * g_dinv[d];
    int pos = atomicAdd(&g_fill[d], 1);
    ((int2*)g_edge4)[pos] = make_int2(s, __float_as_int(nm));
}

// ---------------- device helper: aggregate one node into a float4 ------------
// Rows are even-length and 16B-aligned: meta fetched as int4 pairs
// (2 L1 wavefronts per 4 edges instead of 4).  Pads have norm = 0.
__device__ __forceinline__ float4 agg_node(const float4* __restrict__ h4,
                                           int d, int lane, float4 bv) {
    const int4* ep4 = (const int4*)g_edge4;
    float dv = g_dinv[d];
    float self = dv * dv;

    float4 a0 = __ldg(h4 + (size_t)d * 32 + lane);
    a0.x *= self; a0.y *= self; a0.z *= self; a0.w *= self;
    float4 a1 = make_float4(0.f, 0.f, 0.f, 0.f);
    float4 a2 = make_float4(0.f, 0.f, 0.f, 0.f);
    float4 a3 = make_float4(0.f, 0.f, 0.f, 0.f);

    int i   = g_rowptr[d];
    int end = g_rowptr[d + 1];   // (end - i) is always even

    for (; i + 4 <= end; i += 4) {
        int4 m0 = __ldg(ep4 + (i >> 1));
        int4 m1 = __ldg(ep4 + (i >> 1) + 1);
        float4 h0 = __ldg(h4 + (size_t)m0.x * 32 + lane);
        float4 h1 = __ldg(h4 + (size_t)m0.z * 32 + lane);
        float4 h2 = __ldg(h4 + (size_t)m1.x * 32 + lane);
        float4 h3 = __ldg(h4 + (size_t)m1.z * 32 + lane);
        float n0 = __int_as_float(m0.y), n1 = __int_as_float(m0.w);
        float n2 = __int_as_float(m1.y), n3 = __int_as_float(m1.w);
        a0.x = fmaf(h0.x, n0, a0.x); a0.y = fmaf(h0.y, n0, a0.y);
        a0.z = fmaf(h0.z, n0, a0.z); a0.w = fmaf(h0.w, n0, a0.w);
        a1.x = fmaf(h1.x, n1, a1.x); a1.y = fmaf(h1.y, n1, a1.y);
        a1.z = fmaf(h1.z, n1, a1.z); a1.w = fmaf(h1.w, n1, a1.w);
        a2.x = fmaf(h2.x, n2, a2.x); a2.y = fmaf(h2.y, n2, a2.y);
        a2.z = fmaf(h2.z, n2, a2.z); a2.w = fmaf(h2.w, n2, a2.w);
        a3.x = fmaf(h3.x, n3, a3.x); a3.y = fmaf(h3.y, n3, a3.y);
        a3.z = fmaf(h3.z, n3, a3.z); a3.w = fmaf(h3.w, n3, a3.w);
    }
    if (i < end) {               // exactly 2 edges left
        int4 m0 = __ldg(ep4 + (i >> 1));
        float4 h0 = __ldg(h4 + (size_t)m0.x * 32 + lane);
        float4 h1 = __ldg(h4 + (size_t)m0.z * 32 + lane);
        float n0 = __int_as_float(m0.y), n1 = __int_as_float(m0.w);
        a0.x = fmaf(h0.x, n0, a0.x); a0.y = fmaf(h0.y, n0, a0.y);
        a0.z = fmaf(h0.z, n0, a0.z); a0.w = fmaf(h0.w, n0, a0.w);
        a1.x = fmaf(h1.x, n1, a1.x); a1.y = fmaf(h1.y, n1, a1.y);
        a1.z = fmaf(h1.z, n1, a1.z); a1.w = fmaf(h1.w, n1, a1.w);
    }
    a0.x += a1.x + a2.x + a3.x;
    a0.y += a1.y + a2.y + a3.y;
    a0.z += a1.z + a2.z + a3.z;
    a0.w += a1.w + a2.w + a3.w;

    a0.x = fmaxf(a0.x + bv.x, 0.f);
    a0.y = fmaxf(a0.y + bv.y, 0.f);
    a0.z = fmaxf(a0.z + bv.z, 0.f);
    a0.w = fmaxf(a0.w + bv.w, 0.f);
    return a0;
}

// ---------------- GEMM: H[n,128] = X[n,128] @ W[128,128] ---------------------
__global__ void gemm128_kernel(const float* __restrict__ X,
                               const float* __restrict__ W,
                               float* __restrict__ H, int n) {
    int warp = (blockIdx.x * blockDim.x + threadIdx.x) >> 5;
    int lane = threadIdx.x & 31;
    int r0 = warp * 4;
    if (r0 >= n) return;

    const float4*     X4 = (const float4*)X;
    const ulonglong2* Wp = (const ulonglong2*)W;   // W row = 32 x 16B

    float4 xr[4];
    #pragma unroll
    for (int r = 0; r < 4; r++) {
        int row = (r0 + r < n) ? (r0 + r) : r0;
        xr[r] = __ldcs(X4 + (size_t)row * 32 + lane);
    }

    unsigned long long acc[4][2] = {};

    #pragma unroll 2
    for (int kb = 0; kb < 32; kb++) {
        float a[4][4];
        #pragma unroll
        for (int r = 0; r < 4; r++) {
            a[r][0] = __shfl_sync(0xffffffffu, xr[r].x, kb);
            a[r][1] = __shfl_sync(0xffffffffu, xr[r].y, kb);
            a[r][2] = __shfl_sync(0xffffffffu, xr[r].z, kb);
            a[r][3] = __shfl_sync(0xffffffffu, xr[r].w, kb);
        }
        #pragma unroll
        for (int c = 0; c < 4; c++) {
            ulonglong2 w = __ldg(Wp + (size_t)(kb * 4 + c) * 32 + lane);
            #pragma unroll
            for (int r = 0; r < 4; r++) {
                unsigned long long av = pack2(a[r][c]);
                ffma2(acc[r][0], av, w.x);
                ffma2(acc[r][1], av, w.y);
            }
        }
    }
    #pragma unroll
    for (int r = 0; r < 4; r++) {
        if (r0 + r < n)
            ((ulonglong2*)H)[(size_t)(r0 + r) * 32 + lane] =
                make_ulonglong2(acc[r][0], acc[r][1]);
    }
}

// ------- fused: agg layer-1 (4 nodes/warp) + bias/relu + GEMM with W2 --------
__global__ void agg_gemm_kernel(const float* __restrict__ h,
                                const float* __restrict__ b,
                                const float* __restrict__ W,
                                float* __restrict__ Hout, int n) {
    int warp = (blockIdx.x * blockDim.x + threadIdx.x) >> 5;
    int lane = threadIdx.x & 31;
    int d0 = warp * 4;
    if (d0 >= n) return;

    const float4* h4 = (const float4*)h;
    float4 bv = __ldg((const float4*)b + lane);

    float4 yr[4];
    #pragma unroll
    for (int r = 0; r < 4; r++) {
        int d = d0 + r;
        if (d < n) yr[r] = agg_node(h4, d, lane, bv);
        else       yr[r] = make_float4(0.f, 0.f, 0.f, 0.f);
    }

    const ulonglong2* Wp = (const ulonglong2*)W;
    unsigned long long acc[4][2] = {};

    #pragma unroll 2
    for (int kb = 0; kb < 32; kb++) {
        float a[4][4];
        #pragma unroll
        for (int r = 0; r < 4; r++) {
            a[r][0] = __shfl_sync(0xffffffffu, yr[r].x, kb);
            a[r][1] = __shfl_sync(0xffffffffu, yr[r].y, kb);
            a[r][2] = __shfl_sync(0xffffffffu, yr[r].z, kb);
            a[r][3] = __shfl_sync(0xffffffffu, yr[r].w, kb);
        }
        #pragma unroll
        for (int c = 0; c < 4; c++) {
            ulonglong2 w = __ldg(Wp + (size_t)(kb * 4 + c) * 32 + lane);
            #pragma unroll
            for (int r = 0; r < 4; r++) {
                unsigned long long av = pack2(a[r][c]);
                ffma2(acc[r][0], av, w.x);
                ffma2(acc[r][1], av, w.y);
            }
        }
    }
    #pragma unroll
    for (int r = 0; r < 4; r++) {
        if (d0 + r < n)
            ((ulonglong2*)Hout)[(size_t)(d0 + r) * 32 + lane] =
                make_ulonglong2(acc[r][0], acc[r][1]);
    }
}

// ---------------- final aggregation (layer 2) + bias + relu -> out -----------
__global__ void agg_kernel(const float* __restrict__ h,
                           const float* __restrict__ b,
                           float* __restrict__ out, int n) {
    int d = (int)(((size_t)blockIdx.x * blockDim.x + threadIdx.x) >> 5);
    int lane = threadIdx.x & 31;
    if (d >= n) return;
    float4 bv = __ldg((const float4*)b + lane);
    float4 a = agg_node((const float4*)h, d, lane, bv);
    __stcs((float4*)out + (size_t)d * 32 + lane, a);   // never re-read
}

// ---------------- launch -----------------------------------------------------
extern "C" void kernel_launch(void* const* d_in, const int* in_sizes, int n_in,
                              void* d_out, int out_size) {
    const float* x  = (const float*)d_in[0];
    const int*   ei = (const int*)d_in[1];
    const float* ew = (const float*)d_in[2];
    const float* W1 = (const float*)d_in[3];
    const float* b1 = (const float*)d_in[4];
    const float* W2 = (const float*)d_in[5];
    const float* b2 = (const float*)d_in[6];
    float* out = (float*)d_out;

    const int N = in_sizes[0] / DD;   // 100000
    const int E = in_sizes[2];        // 1600000

    float* h  = nullptr; cudaGetSymbolAddress((void**)&h,  g_h);
    float* h2 = nullptr; cudaGetSymbolAddress((void**)&h2, g_h2);

    // side stream + fork/join events (host-side objects, created once)
    static cudaStream_t sB = nullptr;
    static cudaEvent_t evFork = nullptr, evJoin = nullptr;
    if (sB == nullptr) {
        cudaStreamCreateWithFlags(&sB, cudaStreamNonBlocking);
        cudaEventCreateWithFlags(&evFork, cudaEventDisableTiming);
        cudaEventCreateWithFlags(&evJoin, cudaEventDisableTiming);
    }

    const int T = 256;
    int nodeBlocks = (N + T - 1) / T;
    int edgeBlocks = (E + T - 1) / T;
    int scanBlocks = (N + 1023) / 1024;                    // 98 (< 148 SMs)
    int quadBlocks = (((N + 3) / 4) * 32 + T - 1) / T;     // 4 rows/warp
    int aggBlocks  = (int)(((size_t)N * 32 + T - 1) / T);  // warp/node

    // fork: gemm1 (FMA-bound, deps only x/W1) overlaps LTS-bound pre-chain
    cudaEventRecord(evFork, 0);
    cudaStreamWaitEvent(sB, evFork, 0);
    gemm128_kernel<<<quadBlocks, T, 0, sB>>>(x, W1, h, N);
    cudaEventRecord(evJoin, sB);

    // main stream: degree, dinv, CSR build (shared by both layers)
    init_kernel<<<nodeBlocks, T>>>(ei, N);
    deg_edge_kernel<<<edgeBlocks, T>>>(ei, ew, E);
    scan_all<<<scanBlocks, 256>>>(scanBlocks, N);
    scatter_kernel<<<edgeBlocks, T>>>(ei, ew, E);

    // join: agg_gemm needs both CSR (main) and h (side)
    cudaStreamWaitEvent(0, evJoin, 0);

    // ---- fused: layer-1 aggregation + relu/bias + layer-2 GEMM ----
    agg_gemm_kernel<<<quadBlocks, T>>>(h, b1, W2, h2, N);

    // ---- layer 2 aggregation -> output ----
    agg_kernel<<<aggBlocks, T>>>(h2, b2, out, N);
}